// round 14
// baseline (speedup 1.0000x reference)
#include <cuda_runtime.h>
#include <cuda_bf16.h>
#include <math.h>

// Problem constants: B=8, N=8192, C=256, K=8, nblocks=8, blk=32
#define TOK_TOTAL 65536          // B*N
#define N_TOK     8192
#define C_DIM     256
#define K_NB      8
#define EPS_W     0.05f
#define OME_W     0.95f

// Scratch (allocation-free rule: __device__ globals)
__device__ float          g_s1[(size_t)TOK_TOTAL * C_DIM];  // 64 MB rectify1 out (f32)
__device__ float          g_t [(size_t)TOK_TOTAL * C_DIM];  // 64 MB monarch out (f32)
__device__ __nv_bfloat16  g_th[(size_t)TOK_TOTAL * C_DIM];  // 32 MB bf16 shadow of t
__device__ __nv_bfloat16  g_xh[(size_t)TOK_TOTAL * C_DIM];  // 32 MB bf16 shadow of x
__device__ float          g_w [(size_t)TOK_TOTAL * K_NB];   // eps-scaled softmax weights

// bf16 -> f32 is exact: shift/mask into high mantissa bits (ALU pipe).
__device__ __forceinline__ float bf_lo(unsigned u) { return __uint_as_float(u << 16); }
__device__ __forceinline__ float bf_hi(unsigned u) { return __uint_as_float(u & 0xFFFF0000u); }

// ---- bf16 split-precision helpers for tensor-core monarch -------------------
// pack two f32 into bf16x2 (elem0 -> low half). PTX cvt puts FIRST operand in
// the HIGH half, so pass (y, x).
__device__ __forceinline__ void split2(float2 v, unsigned& hi, unsigned& lo) {
    unsigned h, l;
    asm("cvt.rn.bf16x2.f32 %0, %1, %2;" : "=r"(h) : "f"(v.y), "f"(v.x));
    float rx = v.x - __uint_as_float(h << 16);          // exact residual
    float ry = v.y - __uint_as_float(h & 0xFFFF0000u);  // exact residual
    asm("cvt.rn.bf16x2.f32 %0, %1, %2;" : "=r"(l) : "f"(ry), "f"(rx));
    hi = h; lo = l;
}

__device__ __forceinline__ void mma_bf16(float* d, const unsigned* a,
                                         unsigned b0, unsigned b1) {
    asm volatile(
        "mma.sync.aligned.m16n8k16.row.col.f32.bf16.bf16.f32 "
        "{%0,%1,%2,%3}, {%4,%5,%6,%7}, {%8,%9}, {%0,%1,%2,%3};"
        : "+f"(d[0]), "+f"(d[1]), "+f"(d[2]), "+f"(d[3])
        : "r"(a[0]), "r"(a[1]), "r"(a[2]), "r"(a[3]), "r"(b0), "r"(b1));
}

// ---------------------------------------------------------------------------
// Kernel 0 (prep): blocks [0,256) compute eps*softmax(-distance);
// blocks [256, 256+16384) convert x (f32) -> g_xh (bf16).
// ---------------------------------------------------------------------------
__global__ void prep_k(const float* __restrict__ dist, const float* __restrict__ x) {
    if (blockIdx.x < 256) {
        int tok = blockIdx.x * blockDim.x + threadIdx.x;
        const float4* dp = (const float4*)(dist + (size_t)tok * K_NB);
        float4 a = dp[0], b4 = dp[1];
        float d[8] = {a.x, a.y, a.z, a.w, b4.x, b4.y, b4.z, b4.w};
        float e[8];
        float s = 0.f;
#pragma unroll
        for (int k = 0; k < 8; k++) { e[k] = __expf(-d[k]); s += e[k]; }
        float inv = EPS_W / s;
        float4* wp = (float4*)(g_w + (size_t)tok * K_NB);
        wp[0] = make_float4(e[0]*inv, e[1]*inv, e[2]*inv, e[3]*inv);
        wp[1] = make_float4(e[4]*inv, e[5]*inv, e[6]*inv, e[7]*inv);
    } else {
        size_t i = (size_t)(blockIdx.x - 256) * blockDim.x + threadIdx.x; // float4 id
        float4 f = __ldcs(&((const float4*)x)[i]);
        __nv_bfloat162 h0 = __float22bfloat162_rn(make_float2(f.x, f.y));
        __nv_bfloat162 h1 = __float22bfloat162_rn(make_float2(f.z, f.w));
        uint2 o;
        o.x = *reinterpret_cast<unsigned*>(&h0);
        o.y = *reinterpret_cast<unsigned*>(&h1);
        ((uint2*)g_xh)[i] = o;
    }
}

// ---------------------------------------------------------------------------
// Kernel 1a: rectify1, warp-per-token, barrier-free, batched gathers.
// ---------------------------------------------------------------------------
__global__ void __launch_bounds__(256) rect1_k(
        const float* __restrict__ x,
        const int*   __restrict__ idx) {
    const int lane = threadIdx.x & 31;
    const int warp = threadIdx.x >> 5;
    const int tok  = blockIdx.x * 8 + warp;     // grid = TOK_TOTAL/8
    const int b    = tok >> 13;
    const __nv_bfloat16* xb = g_xh + ((size_t)b << 13) * C_DIM;

    float wv = 0.f; int iv = 0;
    if (lane < 8) {
        wv = g_w[(size_t)tok * 8 + lane];
        iv = idx[(size_t)tok * 8 + lane];
    }
    float wks[8]; const __nv_bfloat16* nps[8];
#pragma unroll
    for (int k = 0; k < 8; k++) {
        wks[k] = __shfl_sync(0xFFFFFFFFu, wv, k);
        nps[k] = xb + (size_t)__shfl_sync(0xFFFFFFFFu, iv, k) * C_DIM;
    }

    const float4* srow = (const float4*)(x + (size_t)tok * C_DIM);
    float4 s0 = __ldcs(&srow[2*lane]), s1 = __ldcs(&srow[2*lane + 1]);
    uint4 nv[8];
#pragma unroll
    for (int k = 0; k < 8; k++) nv[k] = ((const uint4*)nps[k])[lane];

    float4 a0 = make_float4(OME_W*s0.x, OME_W*s0.y, OME_W*s0.z, OME_W*s0.w);
    float4 a1 = make_float4(OME_W*s1.x, OME_W*s1.y, OME_W*s1.z, OME_W*s1.w);
#pragma unroll
    for (int k = 0; k < 8; k++) {
        float wk = wks[k]; uint4 n = nv[k];
        a0.x = fmaf(wk, bf_lo(n.x), a0.x);  a0.y = fmaf(wk, bf_hi(n.x), a0.y);
        a0.z = fmaf(wk, bf_lo(n.y), a0.z);  a0.w = fmaf(wk, bf_hi(n.y), a0.w);
        a1.x = fmaf(wk, bf_lo(n.z), a1.x);  a1.y = fmaf(wk, bf_hi(n.z), a1.y);
        a1.z = fmaf(wk, bf_lo(n.w), a1.z);  a1.w = fmaf(wk, bf_hi(n.w), a1.w);
    }

    float4* orow = (float4*)(g_s1 + (size_t)tok * C_DIM);
    __stcs(&orow[2*lane],     a0);     // read-once stream (monarch_k)
    __stcs(&orow[2*lane + 1], a1);
}

// ---------------------------------------------------------------------------
// Kernel 1b: monarch butterfly on TENSOR CORES (mma.sync m16n8k16 bf16,
// split-precision: D = Ahi*Bhi + Ahi*Blo + Alo*Bhi; lo*lo dropped ~2^-16).
// 512 threads: warps 0-7 = stage1 (block w), warps 8-15 = stage2 (block w).
// Per CTA: 128 tokens in 8 groups of 16, software-pipelined through a
// double-buffered smem tile SB[l][t][r] (the butterfly permutation) with one
// __syncthreads per group. Intermediates stay f32 in SB.
//   stage1: O1[t][q] = sum_p W1[w][q][p] * s1[t][w*32+p]   (A from gmem)
//   SB[l=c&7][t][r=c>>3] = O1 flat channel c = w*32+q
//   stage2: O2[t][s] = sum_r W2[w][s][r] * SB[w][t][r]; out ch = s*8+w
// SB strides: plane P=584, row R=36 floats (<=2-way bank conflicts, 8B align).
// ---------------------------------------------------------------------------
__global__ void __launch_bounds__(512) monarch_k(
        const float* __restrict__ w1,
        const float* __restrict__ w2,
        const float* __restrict__ bias) {
    __shared__ __align__(16) float SB[2][8 * 584];   // 2 x 18688 B

    const int tid  = threadIdx.x;
    const int lane = tid & 31;
    const int warp = tid >> 5;       // 0..15
    const int w    = warp & 7;       // monarch block id for this warp
    const bool s1  = (warp < 8);
    const int grp  = lane >> 2;      // 0..7  (fragment row group)
    const int tig  = lane & 3;       // 0..3  (thread-in-group)
    const int base = blockIdx.x * 128;

    // ---- load + hi/lo-split this warp's 32x32 weight block into B-fragments
    // B col-major (k x n): b0 = (k=2tig(+1), n=grp), b1 = k+8(+9). k-tiles kt,
    // n-tiles nt of 8. W[q][p] row-major, reduction dim contiguous -> float2.
    unsigned Bh[2][4][2], Bl[2][4][2];
    {
        const float* wb = (s1 ? w1 : w2) + (size_t)w * 1024;
#pragma unroll
        for (int kt = 0; kt < 2; kt++)
#pragma unroll
        for (int nt = 0; nt < 4; nt++) {
            const float* rq = wb + (nt*8 + grp)*32 + kt*16 + 2*tig;
            split2(*(const float2*)rq,       Bh[kt][nt][0], Bl[kt][nt][0]);
            split2(*(const float2*)(rq + 8), Bh[kt][nt][1], Bl[kt][nt][1]);
        }
    }
    float bs0[4], bs1[4];
    if (!s1) {
#pragma unroll
        for (int nt = 0; nt < 4; nt++) {
            bs0[nt] = bias[(nt*8 + 2*tig    )*8 + w];
            bs1[nt] = bias[(nt*8 + 2*tig + 1)*8 + w];
        }
    }

#pragma unroll 1
    for (int g = 0; g < 9; g++) {
        if (s1 && g < 8) {
            // ---------------- stage1: group g -> SB[g&1]
            const int tok0 = base + g*16;
            float D[4][4] = {};
#pragma unroll
            for (int kt = 0; kt < 2; kt++) {
                const float* ab = g_s1 + (size_t)(tok0 + grp)*C_DIM
                                + w*32 + kt*16 + 2*tig;
                float2 v0 = *(const float2*)(ab);
                float2 v1 = *(const float2*)(ab + 8*C_DIM);
                float2 v2 = *(const float2*)(ab + 8);
                float2 v3 = *(const float2*)(ab + 8*C_DIM + 8);
                unsigned ah[4], al[4];
                split2(v0, ah[0], al[0]);
                split2(v1, ah[1], al[1]);
                split2(v2, ah[2], al[2]);
                split2(v3, ah[3], al[3]);
#pragma unroll
                for (int nt = 0; nt < 4; nt++) {
                    mma_bf16(D[nt], ah, Bh[kt][nt][0], Bh[kt][nt][1]);
                    mma_bf16(D[nt], ah, Bl[kt][nt][0], Bl[kt][nt][1]);
                    mma_bf16(D[nt], al, Bh[kt][nt][0], Bh[kt][nt][1]);
                }
            }
            // scatter into butterfly layout: c = w*32 + nt*8 + col
            // -> l = col&7 (col = 2tig or 2tig+1), r = w*4 + nt, t = grp(+8)
            float* sb = SB[g & 1];
#pragma unroll
            for (int nt = 0; nt < 4; nt++) {
                const int r = w*4 + nt;
                sb[(2*tig    )*584 + (grp    )*36 + r] = D[nt][0];
                sb[(2*tig + 1)*584 + (grp    )*36 + r] = D[nt][1];
                sb[(2*tig    )*584 + (grp + 8)*36 + r] = D[nt][2];
                sb[(2*tig + 1)*584 + (grp + 8)*36 + r] = D[nt][3];
            }
        }
        if (!s1 && g > 0) {
            // ---------------- stage2: group g-1 from SB[(g-1)&1]
            const int tok0 = base + (g-1)*16;
            const float* sb = SB[(g-1) & 1] + w*584;
            float D[4][4];
#pragma unroll
            for (int nt = 0; nt < 4; nt++) {
                D[nt][0] = bs0[nt]; D[nt][1] = bs1[nt];
                D[nt][2] = bs0[nt]; D[nt][3] = bs1[nt];
            }
#pragma unroll
            for (int kt = 0; kt < 2; kt++) {
                const float* ab = sb + grp*36 + kt*16 + 2*tig;
                float2 v0 = *(const float2*)(ab);
                float2 v1 = *(const float2*)(ab + 8*36);
                float2 v2 = *(const float2*)(ab + 8);
                float2 v3 = *(const float2*)(ab + 8*36 + 8);
                unsigned ah[4], al[4];
                split2(v0, ah[0], al[0]);
                split2(v1, ah[1], al[1]);
                split2(v2, ah[2], al[2]);
                split2(v3, ah[3], al[3]);
#pragma unroll
                for (int nt = 0; nt < 4; nt++) {
                    mma_bf16(D[nt], ah, Bh[kt][nt][0], Bh[kt][nt][1]);
                    mma_bf16(D[nt], ah, Bl[kt][nt][0], Bl[kt][nt][1]);
                    mma_bf16(D[nt], al, Bh[kt][nt][0], Bh[kt][nt][1]);
                }
            }
            // out channel = s*8 + w, s = nt*8 + 2tig (+1)
            const int tok = tok0 + grp;
#pragma unroll
            for (int nt = 0; nt < 4; nt++) {
                const int ch = (nt*8 + 2*tig)*8 + w;
                const size_t o0 = (size_t)tok*C_DIM + ch;
                const size_t o1 = (size_t)(tok + 8)*C_DIM + ch;
                __stcs(&g_t[o0    ], D[nt][0]);
                __stcs(&g_t[o0 + 8], D[nt][1]);
                __stcs(&g_t[o1    ], D[nt][2]);
                __stcs(&g_t[o1 + 8], D[nt][3]);
                g_th[o0    ] = __float2bfloat16_rn(D[nt][0]);
                g_th[o0 + 8] = __float2bfloat16_rn(D[nt][1]);
                g_th[o1    ] = __float2bfloat16_rn(D[nt][2]);
                g_th[o1 + 8] = __float2bfloat16_rn(D[nt][3]);
            }
        }
        __syncthreads();
    }
}

// ---------------------------------------------------------------------------
// Kernel 2: rectify2 on t + rf. Warp-per-token, barrier-free, batched bf16
// gathers.
// ---------------------------------------------------------------------------
__global__ void __launch_bounds__(256) k2_rect_add(
        const float* __restrict__ rf,
        const int*   __restrict__ idx,
        float*       __restrict__ out) {
    const int lane = threadIdx.x & 31;
    const int warp = threadIdx.x >> 5;
    const int tok  = blockIdx.x * 8 + warp;     // grid = TOK_TOTAL/8
    const int b    = tok >> 13;
    const __nv_bfloat16* tb = g_th + ((size_t)b << 13) * C_DIM;

    float wv = 0.f; int iv = 0;
    if (lane < 8) {
        wv = g_w[(size_t)tok * 8 + lane];
        iv = idx[(size_t)tok * 8 + lane];
    }
    float wks[8]; const __nv_bfloat16* nps[8];
#pragma unroll
    for (int k = 0; k < 8; k++) {
        wks[k] = __shfl_sync(0xFFFFFFFFu, wv, k);
        nps[k] = tb + (size_t)__shfl_sync(0xFFFFFFFFu, iv, k) * C_DIM;
    }

    const float4* trow = (const float4*)(g_t + (size_t)tok * C_DIM);
    float4 s0 = __ldcs(&trow[2*lane]), s1 = __ldcs(&trow[2*lane + 1]);
    const float4* rrow = (const float4*)(rf + (size_t)tok * C_DIM);
    float4 r0 = __ldcs(&rrow[2*lane]), r1 = __ldcs(&rrow[2*lane + 1]);
    uint4 nv[8];
#pragma unroll
    for (int k = 0; k < 8; k++) nv[k] = ((const uint4*)nps[k])[lane];

    float4 a0 = make_float4(OME_W*s0.x + r0.x, OME_W*s0.y + r0.y,
                            OME_W*s0.z + r0.z, OME_W*s0.w + r0.w);
    float4 a1 = make_float4(OME_W*s1.x + r1.x, OME_W*s1.y + r1.y,
                            OME_W*s1.z + r1.z, OME_W*s1.w + r1.w);
#pragma unroll
    for (int k = 0; k < 8; k++) {
        float wk = wks[k]; uint4 n = nv[k];
        a0.x = fmaf(wk, bf_lo(n.x), a0.x);  a0.y = fmaf(wk, bf_hi(n.x), a0.y);
        a0.z = fmaf(wk, bf_lo(n.y), a0.z);  a0.w = fmaf(wk, bf_hi(n.y), a0.w);
        a1.x = fmaf(wk, bf_lo(n.z), a1.x);  a1.y = fmaf(wk, bf_hi(n.z), a1.y);
        a1.z = fmaf(wk, bf_lo(n.w), a1.z);  a1.w = fmaf(wk, bf_hi(n.w), a1.w);
    }

    float4* orow = (float4*)(out + (size_t)tok * C_DIM);
    __stcs(&orow[2*lane],     a0);
    __stcs(&orow[2*lane + 1], a1);
}

// ---------------------------------------------------------------------------
extern "C" void kernel_launch(void* const* d_in, const int* in_sizes, int n_in,
                              void* d_out, int out_size) {
    const float* x    = (const float*)d_in[0];
    const float* dist = (const float*)d_in[1];
    const int*   idx  = (const int*)  d_in[2];
    const float* rf   = (const float*)d_in[3];
    const float* w1   = (const float*)d_in[4];
    const float* w2   = (const float*)d_in[5];
    const float* bias = (const float*)d_in[6];
    float* out = (float*)d_out;

    prep_k<<<256 + (TOK_TOTAL * C_DIM / 4) / 256, 256>>>(dist, x);
    rect1_k<<<TOK_TOTAL / 8, 256>>>(x, idx);
    monarch_k<<<TOK_TOTAL / 128, 512>>>(w1, w2, bias);
    k2_rect_add<<<TOK_TOTAL / 8, 256>>>(rf, idx, out);
}

// round 15
// speedup vs baseline: 1.3027x; 1.3027x over previous
#include <cuda_runtime.h>
#include <cuda_bf16.h>
#include <math.h>

// Problem constants: B=8, N=8192, C=256, K=8, nblocks=8, blk=32
#define TOK_TOTAL 65536          // B*N
#define N_TOK     8192
#define C_DIM     256
#define K_NB      8
#define EPS_W     0.05f
#define OME_W     0.95f

// Scratch (allocation-free rule: __device__ globals)
__device__ float          g_s1[(size_t)TOK_TOTAL * C_DIM];  // 64 MB rectify1 out (f32)
__device__ float          g_t [(size_t)TOK_TOTAL * C_DIM];  // 64 MB monarch out (f32)
__device__ __nv_bfloat16  g_th[(size_t)TOK_TOTAL * C_DIM];  // 32 MB bf16 shadow of t
__device__ __nv_bfloat16  g_xh[(size_t)TOK_TOTAL * C_DIM];  // 32 MB bf16 shadow of x
__device__ float          g_w [(size_t)TOK_TOTAL * K_NB];   // eps-scaled softmax weights
// Combined monarch matrix M (256x256), hi/lo bf16 split, stored in mma
// B-fragment order: index ((ntg*16 + kc)*64 + lane*2 + b01)
__device__ unsigned       g_MhF[32768];                     // 128 KB
__device__ unsigned       g_MlF[32768];                     // 128 KB

// bf16 -> f32 is exact: shift/mask into high mantissa bits (ALU pipe).
__device__ __forceinline__ float bf_lo(unsigned u) { return __uint_as_float(u << 16); }
__device__ __forceinline__ float bf_hi(unsigned u) { return __uint_as_float(u & 0xFFFF0000u); }

// pack two f32 into bf16x2 hi + exact-residual lo (elem0 -> low half; PTX cvt
// puts FIRST operand in the HIGH half, so pass (y, x)). Validated in R14.
__device__ __forceinline__ void split2(float2 v, unsigned& hi, unsigned& lo) {
    unsigned h, l;
    asm("cvt.rn.bf16x2.f32 %0, %1, %2;" : "=r"(h) : "f"(v.y), "f"(v.x));
    float rx = v.x - __uint_as_float(h << 16);          // exact residual
    float ry = v.y - __uint_as_float(h & 0xFFFF0000u);  // exact residual
    asm("cvt.rn.bf16x2.f32 %0, %1, %2;" : "=r"(l) : "f"(ry), "f"(rx));
    hi = h; lo = l;
}
__device__ __forceinline__ unsigned pack_bf(float lo_e, float hi_e) {
    unsigned r;
    asm("cvt.rn.bf16x2.f32 %0, %1, %2;" : "=r"(r) : "f"(hi_e), "f"(lo_e));
    return r;
}
__device__ __forceinline__ void mma_bf16(float* d, const unsigned* a,
                                         unsigned b0, unsigned b1) {
    asm volatile(
        "mma.sync.aligned.m16n8k16.row.col.f32.bf16.bf16.f32 "
        "{%0,%1,%2,%3}, {%4,%5,%6,%7}, {%8,%9}, {%0,%1,%2,%3};"
        : "+f"(d[0]), "+f"(d[1]), "+f"(d[2]), "+f"(d[3])
        : "r"(a[0]), "r"(a[1]), "r"(a[2]), "r"(a[3]), "r"(b0), "r"(b1));
}

// ---------------------------------------------------------------------------
// Kernel 0 (prep): blocks [0,256) compute eps*softmax(-distance);
// blocks [256, 256+16384) convert x (f32) -> g_xh (bf16).
// ---------------------------------------------------------------------------
__global__ void prep_k(const float* __restrict__ dist, const float* __restrict__ x) {
    if (blockIdx.x < 256) {
        int tok = blockIdx.x * blockDim.x + threadIdx.x;
        const float4* dp = (const float4*)(dist + (size_t)tok * K_NB);
        float4 a = dp[0], b4 = dp[1];
        float d[8] = {a.x, a.y, a.z, a.w, b4.x, b4.y, b4.z, b4.w};
        float e[8];
        float s = 0.f;
#pragma unroll
        for (int k = 0; k < 8; k++) { e[k] = __expf(-d[k]); s += e[k]; }
        float inv = EPS_W / s;
        float4* wp = (float4*)(g_w + (size_t)tok * K_NB);
        wp[0] = make_float4(e[0]*inv, e[1]*inv, e[2]*inv, e[3]*inv);
        wp[1] = make_float4(e[4]*inv, e[5]*inv, e[6]*inv, e[7]*inv);
    } else {
        size_t i = (size_t)(blockIdx.x - 256) * blockDim.x + threadIdx.x; // float4 id
        float4 f = __ldcs(&((const float4*)x)[i]);
        __nv_bfloat162 h0 = __float22bfloat162_rn(make_float2(f.x, f.y));
        __nv_bfloat162 h1 = __float22bfloat162_rn(make_float2(f.z, f.w));
        uint2 o;
        o.x = *reinterpret_cast<unsigned*>(&h0);
        o.y = *reinterpret_cast<unsigned*>(&h1);
        ((uint2*)g_xh)[i] = o;
    }
}

// ---------------------------------------------------------------------------
// Kernel 0b: build combined monarch matrix M (out 256 x in 256), split to
// bf16 hi/lo, stored directly in mma B-fragment order.
//   n = s*8+l (out), k = a*32+p (in):
//   M[n][k] = sum_{j=0..3} w2[l,s,4a+j] * w1[a, 8j+l, p]
// One thread per packed bf16x2 output (2 consecutive k).
// ---------------------------------------------------------------------------
__global__ void mbuild_k(const float* __restrict__ w1,
                         const float* __restrict__ w2) {
    const int u = blockIdx.x * blockDim.x + threadIdx.x;   // 0..32767
    const int b01  = u & 1;
    const int lane = (u >> 1) & 31;
    const int kc   = (u >> 6) & 15;
    const int ntg  = u >> 10;                 // 0..31
    const int n = ntg * 8 + (lane >> 2);
    const int k = kc * 16 + b01 * 8 + 2 * (lane & 3);

    const int l = n & 7, s = n >> 3;
    const int a = k >> 5, p = k & 31;
    const float* w2r = w2 + l * 1024 + s * 32 + 4 * a;
    const float* w1b = w1 + a * 1024 + l * 32 + p;   // + j*256 gives row 8j+l
    float m0 = 0.f, m1 = 0.f;
#pragma unroll
    for (int j = 0; j < 4; j++) {
        float c = w2r[j];
        m0 = fmaf(c, w1b[j * 256],     m0);
        m1 = fmaf(c, w1b[j * 256 + 1], m1);
    }
    unsigned hi, lo;
    split2(make_float2(m0, m1), hi, lo);
    g_MhF[u] = hi;
    g_MlF[u] = lo;
}

// ---------------------------------------------------------------------------
// Kernel 1a: rectify1, warp-per-token, barrier-free, batched gathers.
// ---------------------------------------------------------------------------
__global__ void __launch_bounds__(256) rect1_k(
        const float* __restrict__ x,
        const int*   __restrict__ idx) {
    const int lane = threadIdx.x & 31;
    const int warp = threadIdx.x >> 5;
    const int tok  = blockIdx.x * 8 + warp;     // grid = TOK_TOTAL/8
    const int b    = tok >> 13;
    const __nv_bfloat16* xb = g_xh + ((size_t)b << 13) * C_DIM;

    float wv = 0.f; int iv = 0;
    if (lane < 8) {
        wv = g_w[(size_t)tok * 8 + lane];
        iv = idx[(size_t)tok * 8 + lane];
    }
    float wks[8]; const __nv_bfloat16* nps[8];
#pragma unroll
    for (int k = 0; k < 8; k++) {
        wks[k] = __shfl_sync(0xFFFFFFFFu, wv, k);
        nps[k] = xb + (size_t)__shfl_sync(0xFFFFFFFFu, iv, k) * C_DIM;
    }

    const float4* srow = (const float4*)(x + (size_t)tok * C_DIM);
    float4 s0 = __ldcs(&srow[2*lane]), s1 = __ldcs(&srow[2*lane + 1]);
    uint4 nv[8];
#pragma unroll
    for (int k = 0; k < 8; k++) nv[k] = ((const uint4*)nps[k])[lane];

    float4 a0 = make_float4(OME_W*s0.x, OME_W*s0.y, OME_W*s0.z, OME_W*s0.w);
    float4 a1 = make_float4(OME_W*s1.x, OME_W*s1.y, OME_W*s1.z, OME_W*s1.w);
#pragma unroll
    for (int k = 0; k < 8; k++) {
        float wk = wks[k]; uint4 n = nv[k];
        a0.x = fmaf(wk, bf_lo(n.x), a0.x);  a0.y = fmaf(wk, bf_hi(n.x), a0.y);
        a0.z = fmaf(wk, bf_lo(n.y), a0.z);  a0.w = fmaf(wk, bf_hi(n.y), a0.w);
        a1.x = fmaf(wk, bf_lo(n.z), a1.x);  a1.y = fmaf(wk, bf_hi(n.z), a1.y);
        a1.z = fmaf(wk, bf_lo(n.w), a1.z);  a1.w = fmaf(wk, bf_hi(n.w), a1.w);
    }

    float4* orow = (float4*)(g_s1 + (size_t)tok * C_DIM);
    __stcs(&orow[2*lane],     a0);     // read-once stream (gemm_k)
    __stcs(&orow[2*lane + 1], a1);
}

// ---------------------------------------------------------------------------
// Kernel 1b: monarch as ONE dense 256x256 GEMM on tensor cores.
// Y[tok][n] = sum_k s1[tok][k] * M[n][k] + bias[n]
// bf16 split-precision: D = Ah*Bh + Ah*Bl + Al*Bh (lo*lo dropped, ~2^-16).
// CTA = 64 tokens x 256 outs; 8 warps, warp w owns n-slice [w*32, w*32+32);
// warp tile m64 x n32, k streamed in 16-wide chunks through double-buffered
// smem (rows padded to 20 floats -> <=2-way LDS conflicts). B fragments come
// straight from g_MhF/g_MlF (fragment-ordered, coalesced LDG.64, L2-resident).
// ---------------------------------------------------------------------------
__global__ void __launch_bounds__(256) gemm_k(const float* __restrict__ bias) {
    __shared__ __align__(16) float As[2][64][20];

    const int tid  = threadIdx.x;
    const int lane = tid & 31;
    const int w    = tid >> 5;        // warp 0..7 -> n-slice
    const int grp  = lane >> 2;
    const int tig  = lane & 3;
    const int tok0 = blockIdx.x * 64;

    // bias per (nt, col-pair)
    float bs[4][2];
#pragma unroll
    for (int nt = 0; nt < 4; nt++) {
        const int c = w*32 + nt*8 + 2*tig;
        bs[nt][0] = bias[c];
        bs[nt][1] = bias[c + 1];
    }
    // D[mg][nt][4], init with bias (d0,d1 = row grp; d2,d3 = row grp+8)
    float D[4][4][4];
#pragma unroll
    for (int mg = 0; mg < 4; mg++)
#pragma unroll
    for (int nt = 0; nt < 4; nt++) {
        D[mg][nt][0] = bs[nt][0]; D[mg][nt][1] = bs[nt][1];
        D[mg][nt][2] = bs[nt][0]; D[mg][nt][3] = bs[nt][1];
    }

    // A staging role: thread loads one float4 of the 64x16 chunk
    const int arow = tid >> 2;
    const int acol = (tid & 3) * 4;
    const float* agp = g_s1 + (size_t)(tok0 + arow) * C_DIM + acol;

    float4 pf = __ldcs((const float4*)(agp));
    *(float4*)&As[0][arow][acol] = pf;

#pragma unroll 1
    for (int c = 0; c < 16; c++) {
        if (c < 15) pf = __ldcs((const float4*)(agp + (c + 1) * 16));
        __syncthreads();   // As[c&1] visible; reads of chunk c-1 complete

        // B fragments for this chunk (coalesced LDG.64, L2-resident)
        uint2 BH[4], BL[4];
#pragma unroll
        for (int nt = 0; nt < 4; nt++) {
            const int bi = (((w*4 + nt)*16 + c) << 6) + lane*2;
            BH[nt] = *(const uint2*)&g_MhF[bi];
            BL[nt] = *(const uint2*)&g_MlF[bi];
        }

#pragma unroll
        for (int mg = 0; mg < 4; mg++) {
            const float* ar = &As[c & 1][mg*16 + grp][0];
            float2 v0 = *(const float2*)(ar + 2*tig);            // row grp,   k
            float2 v1 = *(const float2*)(ar + 8*20 + 2*tig);     // row grp+8, k
            float2 v2 = *(const float2*)(ar + 2*tig + 8);        // row grp,   k+8
            float2 v3 = *(const float2*)(ar + 8*20 + 2*tig + 8); // row grp+8, k+8
            unsigned ah[4], al[4];
            split2(v0, ah[0], al[0]);
            split2(v1, ah[1], al[1]);
            split2(v2, ah[2], al[2]);
            split2(v3, ah[3], al[3]);
#pragma unroll
            for (int nt = 0; nt < 4; nt++) {
                mma_bf16(D[mg][nt], ah, BH[nt].x, BH[nt].y);
                mma_bf16(D[mg][nt], ah, BL[nt].x, BL[nt].y);
                mma_bf16(D[mg][nt], al, BH[nt].x, BH[nt].y);
            }
        }
        if (c < 15) *(float4*)&As[(c + 1) & 1][arow][acol] = pf;
    }

    // store: rows tok0+mg*16+grp (+8), cols w*32+nt*8+2tig (+1)
#pragma unroll
    for (int mg = 0; mg < 4; mg++) {
        const int row = tok0 + mg*16 + grp;
#pragma unroll
        for (int nt = 0; nt < 4; nt++) {
            const int cb = w*32 + nt*8 + 2*tig;
            const size_t o0 = (size_t)row * C_DIM + cb;
            const size_t o1 = (size_t)(row + 8) * C_DIM + cb;
            __stcs((float2*)&g_t[o0], make_float2(D[mg][nt][0], D[mg][nt][1]));
            __stcs((float2*)&g_t[o1], make_float2(D[mg][nt][2], D[mg][nt][3]));
            *(unsigned*)&g_th[o0] = pack_bf(D[mg][nt][0], D[mg][nt][1]);
            *(unsigned*)&g_th[o1] = pack_bf(D[mg][nt][2], D[mg][nt][3]);
        }
    }
}

// ---------------------------------------------------------------------------
// Kernel 2: rectify2 on t + rf. Warp-per-token, barrier-free, batched bf16
// gathers.
// ---------------------------------------------------------------------------
__global__ void __launch_bounds__(256) k2_rect_add(
        const float* __restrict__ rf,
        const int*   __restrict__ idx,
        float*       __restrict__ out) {
    const int lane = threadIdx.x & 31;
    const int warp = threadIdx.x >> 5;
    const int tok  = blockIdx.x * 8 + warp;     // grid = TOK_TOTAL/8
    const int b    = tok >> 13;
    const __nv_bfloat16* tb = g_th + ((size_t)b << 13) * C_DIM;

    float wv = 0.f; int iv = 0;
    if (lane < 8) {
        wv = g_w[(size_t)tok * 8 + lane];
        iv = idx[(size_t)tok * 8 + lane];
    }
    float wks[8]; const __nv_bfloat16* nps[8];
#pragma unroll
    for (int k = 0; k < 8; k++) {
        wks[k] = __shfl_sync(0xFFFFFFFFu, wv, k);
        nps[k] = tb + (size_t)__shfl_sync(0xFFFFFFFFu, iv, k) * C_DIM;
    }

    const float4* trow = (const float4*)(g_t + (size_t)tok * C_DIM);
    float4 s0 = __ldcs(&trow[2*lane]), s1 = __ldcs(&trow[2*lane + 1]);
    const float4* rrow = (const float4*)(rf + (size_t)tok * C_DIM);
    float4 r0 = __ldcs(&rrow[2*lane]), r1 = __ldcs(&rrow[2*lane + 1]);
    uint4 nv[8];
#pragma unroll
    for (int k = 0; k < 8; k++) nv[k] = ((const uint4*)nps[k])[lane];

    float4 a0 = make_float4(OME_W*s0.x + r0.x, OME_W*s0.y + r0.y,
                            OME_W*s0.z + r0.z, OME_W*s0.w + r0.w);
    float4 a1 = make_float4(OME_W*s1.x + r1.x, OME_W*s1.y + r1.y,
                            OME_W*s1.z + r1.z, OME_W*s1.w + r1.w);
#pragma unroll
    for (int k = 0; k < 8; k++) {
        float wk = wks[k]; uint4 n = nv[k];
        a0.x = fmaf(wk, bf_lo(n.x), a0.x);  a0.y = fmaf(wk, bf_hi(n.x), a0.y);
        a0.z = fmaf(wk, bf_lo(n.y), a0.z);  a0.w = fmaf(wk, bf_hi(n.y), a0.w);
        a1.x = fmaf(wk, bf_lo(n.z), a1.x);  a1.y = fmaf(wk, bf_hi(n.z), a1.y);
        a1.z = fmaf(wk, bf_lo(n.w), a1.z);  a1.w = fmaf(wk, bf_hi(n.w), a1.w);
    }

    float4* orow = (float4*)(out + (size_t)tok * C_DIM);
    __stcs(&orow[2*lane],     a0);
    __stcs(&orow[2*lane + 1], a1);
}

// ---------------------------------------------------------------------------
extern "C" void kernel_launch(void* const* d_in, const int* in_sizes, int n_in,
                              void* d_out, int out_size) {
    const float* x    = (const float*)d_in[0];
    const float* dist = (const float*)d_in[1];
    const int*   idx  = (const int*)  d_in[2];
    const float* rf   = (const float*)d_in[3];
    const float* w1   = (const float*)d_in[4];
    const float* w2   = (const float*)d_in[5];
    const float* bias = (const float*)d_in[6];
    float* out = (float*)d_out;

    prep_k<<<256 + (TOK_TOTAL * C_DIM / 4) / 256, 256>>>(dist, x);
    mbuild_k<<<128, 256>>>(w1, w2);
    rect1_k<<<TOK_TOTAL / 8, 256>>>(x, idx);
    gemm_k<<<TOK_TOTAL / 64, 256>>>(bias);
    k2_rect_add<<<TOK_TOTAL / 8, 256>>>(rf, idx, out);
}

// round 16
// speedup vs baseline: 1.3989x; 1.0738x over previous
#include <cuda_runtime.h>
#include <cuda_bf16.h>
#include <math.h>

// Problem constants: B=8, N=8192, C=256, K=8, nblocks=8, blk=32
#define TOK_TOTAL 65536          // B*N
#define N_TOK     8192
#define C_DIM     256
#define K_NB      8
#define EPS_W     0.05f
#define OME_W     0.95f

// Scratch (allocation-free rule: __device__ globals)
__device__ unsigned       g_s1h[(size_t)TOK_TOTAL * 128];   // 32 MB s1 bf16 hi (bf16x2)
__device__ unsigned       g_s1l[(size_t)TOK_TOTAL * 128];   // 32 MB s1 bf16 lo (bf16x2)
__device__ float          g_t [(size_t)TOK_TOTAL * C_DIM];  // 64 MB monarch out (f32)
__device__ __nv_bfloat16  g_th[(size_t)TOK_TOTAL * C_DIM];  // 32 MB bf16 shadow of t
__device__ __nv_bfloat16  g_xh[(size_t)TOK_TOTAL * C_DIM];  // 32 MB bf16 shadow of x
__device__ float          g_w [(size_t)TOK_TOTAL * K_NB];   // eps-scaled softmax weights
// Combined monarch matrix M (256x256) in mma B-fragment order, hi/lo
// interleaved per fragment pair: uint4 = {b0_hi, b1_hi, b0_lo, b1_lo}.
__device__ unsigned       g_MF[131072];                     // 512 KB

// bf16 -> f32 is exact: shift/mask into high mantissa bits (ALU pipe).
__device__ __forceinline__ float bf_lo(unsigned u) { return __uint_as_float(u << 16); }
__device__ __forceinline__ float bf_hi(unsigned u) { return __uint_as_float(u & 0xFFFF0000u); }

// pack two f32 into bf16x2 hi + exact-residual lo (elem0 -> low half; PTX cvt
// puts FIRST operand in the HIGH half, so pass (y, x)). Validated in R14/R15.
__device__ __forceinline__ void split2(float2 v, unsigned& hi, unsigned& lo) {
    unsigned h, l;
    asm("cvt.rn.bf16x2.f32 %0, %1, %2;" : "=r"(h) : "f"(v.y), "f"(v.x));
    float rx = v.x - __uint_as_float(h << 16);          // exact residual
    float ry = v.y - __uint_as_float(h & 0xFFFF0000u);  // exact residual
    asm("cvt.rn.bf16x2.f32 %0, %1, %2;" : "=r"(l) : "f"(ry), "f"(rx));
    hi = h; lo = l;
}
__device__ __forceinline__ unsigned pack_bf(float lo_e, float hi_e) {
    unsigned r;
    asm("cvt.rn.bf16x2.f32 %0, %1, %2;" : "=r"(r) : "f"(hi_e), "f"(lo_e));
    return r;
}
__device__ __forceinline__ void mma_bf16(float* d, const unsigned* a,
                                         unsigned b0, unsigned b1) {
    asm volatile(
        "mma.sync.aligned.m16n8k16.row.col.f32.bf16.bf16.f32 "
        "{%0,%1,%2,%3}, {%4,%5,%6,%7}, {%8,%9}, {%0,%1,%2,%3};"
        : "+f"(d[0]), "+f"(d[1]), "+f"(d[2]), "+f"(d[3])
        : "r"(a[0]), "r"(a[1]), "r"(a[2]), "r"(a[3]), "r"(b0), "r"(b1));
}

// ---------------------------------------------------------------------------
// Kernel 0 (prep): blocks [0,256) compute eps*softmax(-distance);
// blocks [256, 256+16384) convert x (f32) -> g_xh (bf16).
// ---------------------------------------------------------------------------
__global__ void prep_k(const float* __restrict__ dist, const float* __restrict__ x) {
    if (blockIdx.x < 256) {
        int tok = blockIdx.x * blockDim.x + threadIdx.x;
        const float4* dp = (const float4*)(dist + (size_t)tok * K_NB);
        float4 a = dp[0], b4 = dp[1];
        float d[8] = {a.x, a.y, a.z, a.w, b4.x, b4.y, b4.z, b4.w};
        float e[8];
        float s = 0.f;
#pragma unroll
        for (int k = 0; k < 8; k++) { e[k] = __expf(-d[k]); s += e[k]; }
        float inv = EPS_W / s;
        float4* wp = (float4*)(g_w + (size_t)tok * K_NB);
        wp[0] = make_float4(e[0]*inv, e[1]*inv, e[2]*inv, e[3]*inv);
        wp[1] = make_float4(e[4]*inv, e[5]*inv, e[6]*inv, e[7]*inv);
    } else {
        size_t i = (size_t)(blockIdx.x - 256) * blockDim.x + threadIdx.x; // float4 id
        float4 f = __ldcs(&((const float4*)x)[i]);
        __nv_bfloat162 h0 = __float22bfloat162_rn(make_float2(f.x, f.y));
        __nv_bfloat162 h1 = __float22bfloat162_rn(make_float2(f.z, f.w));
        uint2 o;
        o.x = *reinterpret_cast<unsigned*>(&h0);
        o.y = *reinterpret_cast<unsigned*>(&h1);
        ((uint2*)g_xh)[i] = o;
    }
}

// ---------------------------------------------------------------------------
// Kernel 0b: build combined monarch matrix M (out 256 x in 256), split to
// bf16 hi/lo, stored in interleaved mma B-fragment order.
//   n = s*8+l (out), k = a*32+p (in):
//   M[n][k] = sum_{j=0..3} w2[l,s,4a+j] * w1[a, 8j+l, p]
// Thread u: b01 = u&1, lane = (u>>1)&31, kc = (u>>6)&15, ntg = u>>10;
// fragment-pair index fp = u>>1; uint4 slot g_MF[fp*4 + {b01, 2+b01}].
// ---------------------------------------------------------------------------
__global__ void mbuild_k(const float* __restrict__ w1,
                         const float* __restrict__ w2) {
    const int u = blockIdx.x * blockDim.x + threadIdx.x;   // 0..32767
    const int b01  = u & 1;
    const int lane = (u >> 1) & 31;
    const int kc   = (u >> 6) & 15;
    const int ntg  = u >> 10;                 // 0..31
    const int n = ntg * 8 + (lane >> 2);
    const int k = kc * 16 + b01 * 8 + 2 * (lane & 3);

    const int l = n & 7, s = n >> 3;
    const int a = k >> 5, p = k & 31;
    const float* w2r = w2 + l * 1024 + s * 32 + 4 * a;
    const float* w1b = w1 + a * 1024 + l * 32 + p;   // + j*256 gives row 8j+l
    float m0 = 0.f, m1 = 0.f;
#pragma unroll
    for (int j = 0; j < 4; j++) {
        float c = w2r[j];
        m0 = fmaf(c, w1b[j * 256],     m0);
        m1 = fmaf(c, w1b[j * 256 + 1], m1);
    }
    unsigned hi, lo;
    split2(make_float2(m0, m1), hi, lo);
    g_MF[(u >> 1) * 4 + b01]     = hi;
    g_MF[(u >> 1) * 4 + 2 + b01] = lo;
}

// ---------------------------------------------------------------------------
// Kernel 1a: rectify1, warp-per-token, barrier-free, batched gathers.
// Output: s1 pre-split into bf16 hi/lo planes (exact residual), so gemm_k's
// hot loop needs ZERO conversion work. Split cost lands here (DRAM-bound,
// ALU idle).
// ---------------------------------------------------------------------------
__global__ void __launch_bounds__(256) rect1_k(
        const float* __restrict__ x,
        const int*   __restrict__ idx) {
    const int lane = threadIdx.x & 31;
    const int warp = threadIdx.x >> 5;
    const int tok  = blockIdx.x * 8 + warp;     // grid = TOK_TOTAL/8
    const int b    = tok >> 13;
    const __nv_bfloat16* xb = g_xh + ((size_t)b << 13) * C_DIM;

    float wv = 0.f; int iv = 0;
    if (lane < 8) {
        wv = g_w[(size_t)tok * 8 + lane];
        iv = idx[(size_t)tok * 8 + lane];
    }
    float wks[8]; const __nv_bfloat16* nps[8];
#pragma unroll
    for (int k = 0; k < 8; k++) {
        wks[k] = __shfl_sync(0xFFFFFFFFu, wv, k);
        nps[k] = xb + (size_t)__shfl_sync(0xFFFFFFFFu, iv, k) * C_DIM;
    }

    const float4* srow = (const float4*)(x + (size_t)tok * C_DIM);
    float4 s0 = __ldcs(&srow[2*lane]), s1 = __ldcs(&srow[2*lane + 1]);
    uint4 nv[8];
#pragma unroll
    for (int k = 0; k < 8; k++) nv[k] = ((const uint4*)nps[k])[lane];

    float4 a0 = make_float4(OME_W*s0.x, OME_W*s0.y, OME_W*s0.z, OME_W*s0.w);
    float4 a1 = make_float4(OME_W*s1.x, OME_W*s1.y, OME_W*s1.z, OME_W*s1.w);
#pragma unroll
    for (int k = 0; k < 8; k++) {
        float wk = wks[k]; uint4 n = nv[k];
        a0.x = fmaf(wk, bf_lo(n.x), a0.x);  a0.y = fmaf(wk, bf_hi(n.x), a0.y);
        a0.z = fmaf(wk, bf_lo(n.y), a0.z);  a0.w = fmaf(wk, bf_hi(n.y), a0.w);
        a1.x = fmaf(wk, bf_lo(n.z), a1.x);  a1.y = fmaf(wk, bf_hi(n.z), a1.y);
        a1.z = fmaf(wk, bf_lo(n.w), a1.z);  a1.w = fmaf(wk, bf_hi(n.w), a1.w);
    }

    unsigned h0,h1,h2,h3, l0,l1,l2,l3;
    split2(make_float2(a0.x, a0.y), h0, l0);
    split2(make_float2(a0.z, a0.w), h1, l1);
    split2(make_float2(a1.x, a1.y), h2, l2);
    split2(make_float2(a1.z, a1.w), h3, l3);
    __stcs(&((uint4*)g_s1h)[(size_t)tok * 32 + lane], make_uint4(h0,h1,h2,h3));
    __stcs(&((uint4*)g_s1l)[(size_t)tok * 32 + lane], make_uint4(l0,l1,l2,l3));
}

// ---------------------------------------------------------------------------
// Kernel 1b: monarch as ONE dense 256x256 GEMM on tensor cores.
// Y[tok][n] = sum_k s1[tok][k] * M[n][k] + bias[n]
// bf16 split-precision: D = Ah*Bh + Ah*Bl + Al*Bh (lo*lo dropped, ~2^-16).
// A arrives PRE-SPLIT (g_s1h/g_s1l) -> hot loop is pure LDS.32 + mma.
// CTA = 64 tokens x 256 outs; warp w owns n-slice [w*32, w*32+32), tile
// m64 x n32; k streamed in 16-wide chunks, double-buffered smem, row pad 12
// uints => conflict-free fragment LDS. B: one LDG.128 per nt per chunk
// (hi/lo interleaved, L2-resident).
// ---------------------------------------------------------------------------
__global__ void __launch_bounds__(256, 2) gemm_k(const float* __restrict__ bias) {
    __shared__ unsigned Ash[2][64][12];
    __shared__ unsigned Asl[2][64][12];

    const int tid  = threadIdx.x;
    const int lane = tid & 31;
    const int w    = tid >> 5;        // warp 0..7 -> n-slice
    const int grp  = lane >> 2;
    const int tig  = lane & 3;
    const int tok0 = blockIdx.x * 64;

    // bias per (nt, col-pair)
    float bs[4][2];
#pragma unroll
    for (int nt = 0; nt < 4; nt++) {
        const int c = w*32 + nt*8 + 2*tig;
        bs[nt][0] = bias[c];
        bs[nt][1] = bias[c + 1];
    }
    // D[mg][nt][4], init with bias (d0,d1 = row grp; d2,d3 = row grp+8)
    float D[4][4][4];
#pragma unroll
    for (int mg = 0; mg < 4; mg++)
#pragma unroll
    for (int nt = 0; nt < 4; nt++) {
        D[mg][nt][0] = bs[nt][0]; D[mg][nt][1] = bs[nt][1];
        D[mg][nt][2] = bs[nt][0]; D[mg][nt][3] = bs[nt][1];
    }

    // A staging role: thread loads one uint2 (4 bf16 ch) per plane per chunk
    const int arow = tid >> 2;        // 0..63
    const int aq   = tid & 3;         // 0..3
    const uint2* hp = (const uint2*)g_s1h + (size_t)(tok0 + arow) * 64 + aq;
    const uint2* lp = (const uint2*)g_s1l + (size_t)(tok0 + arow) * 64 + aq;

    uint2 pfh = __ldcs(hp), pfl = __ldcs(lp);
    *(uint2*)&Ash[0][arow][2*aq] = pfh;
    *(uint2*)&Asl[0][arow][2*aq] = pfl;

#pragma unroll 1
    for (int c = 0; c < 16; c++) {
        if (c < 15) {
            pfh = __ldcs(hp + (c + 1) * 4);
            pfl = __ldcs(lp + (c + 1) * 4);
        }
        __syncthreads();   // As[c&1] visible; reads of chunk c-1 complete

        // B fragments: hi/lo interleaved, one LDG.128 per nt (L2-resident)
        uint4 BF[4];
#pragma unroll
        for (int nt = 0; nt < 4; nt++)
            BF[nt] = ((const uint4*)g_MF)[(((w*4 + nt)*16 + c) << 5) + lane];

#pragma unroll
        for (int mg = 0; mg < 4; mg++) {
            const unsigned* arh = &Ash[c & 1][mg*16 + grp][0];
            const unsigned* arl = &Asl[c & 1][mg*16 + grp][0];
            unsigned ah[4], al[4];
            ah[0] = arh[tig];          ah[1] = arh[8*12 + tig];
            ah[2] = arh[tig + 4];      ah[3] = arh[8*12 + tig + 4];
            al[0] = arl[tig];          al[1] = arl[8*12 + tig];
            al[2] = arl[tig + 4];      al[3] = arl[8*12 + tig + 4];
#pragma unroll
            for (int nt = 0; nt < 4; nt++) {
                mma_bf16(D[mg][nt], ah, BF[nt].x, BF[nt].y);
                mma_bf16(D[mg][nt], ah, BF[nt].z, BF[nt].w);
                mma_bf16(D[mg][nt], al, BF[nt].x, BF[nt].y);
            }
        }
        if (c < 15) {
            *(uint2*)&Ash[(c + 1) & 1][arow][2*aq] = pfh;
            *(uint2*)&Asl[(c + 1) & 1][arow][2*aq] = pfl;
        }
    }

    // store: rows tok0+mg*16+grp (+8), cols w*32+nt*8+2tig (+1)
#pragma unroll
    for (int mg = 0; mg < 4; mg++) {
        const int row = tok0 + mg*16 + grp;
#pragma unroll
        for (int nt = 0; nt < 4; nt++) {
            const int cb = w*32 + nt*8 + 2*tig;
            const size_t o0 = (size_t)row * C_DIM + cb;
            const size_t o1 = (size_t)(row + 8) * C_DIM + cb;
            __stcs((float2*)&g_t[o0], make_float2(D[mg][nt][0], D[mg][nt][1]));
            __stcs((float2*)&g_t[o1], make_float2(D[mg][nt][2], D[mg][nt][3]));
            *(unsigned*)&g_th[o0] = pack_bf(D[mg][nt][0], D[mg][nt][1]);
            *(unsigned*)&g_th[o1] = pack_bf(D[mg][nt][2], D[mg][nt][3]);
        }
    }
}

// ---------------------------------------------------------------------------
// Kernel 2: rectify2 on t + rf. Warp-per-token, barrier-free, batched bf16
// gathers.
// ---------------------------------------------------------------------------
__global__ void __launch_bounds__(256) k2_rect_add(
        const float* __restrict__ rf,
        const int*   __restrict__ idx,
        float*       __restrict__ out) {
    const int lane = threadIdx.x & 31;
    const int warp = threadIdx.x >> 5;
    const int tok  = blockIdx.x * 8 + warp;     // grid = TOK_TOTAL/8
    const int b    = tok >> 13;
    const __nv_bfloat16* tb = g_th + ((size_t)b << 13) * C_DIM;

    float wv = 0.f; int iv = 0;
    if (lane < 8) {
        wv = g_w[(size_t)tok * 8 + lane];
        iv = idx[(size_t)tok * 8 + lane];
    }
    float wks[8]; const __nv_bfloat16* nps[8];
#pragma unroll
    for (int k = 0; k < 8; k++) {
        wks[k] = __shfl_sync(0xFFFFFFFFu, wv, k);
        nps[k] = tb + (size_t)__shfl_sync(0xFFFFFFFFu, iv, k) * C_DIM;
    }

    const float4* trow = (const float4*)(g_t + (size_t)tok * C_DIM);
    float4 s0 = __ldcs(&trow[2*lane]), s1 = __ldcs(&trow[2*lane + 1]);
    const float4* rrow = (const float4*)(rf + (size_t)tok * C_DIM);
    float4 r0 = __ldcs(&rrow[2*lane]), r1 = __ldcs(&rrow[2*lane + 1]);
    uint4 nv[8];
#pragma unroll
    for (int k = 0; k < 8; k++) nv[k] = ((const uint4*)nps[k])[lane];

    float4 a0 = make_float4(OME_W*s0.x + r0.x, OME_W*s0.y + r0.y,
                            OME_W*s0.z + r0.z, OME_W*s0.w + r0.w);
    float4 a1 = make_float4(OME_W*s1.x + r1.x, OME_W*s1.y + r1.y,
                            OME_W*s1.z + r1.z, OME_W*s1.w + r1.w);
#pragma unroll
    for (int k = 0; k < 8; k++) {
        float wk = wks[k]; uint4 n = nv[k];
        a0.x = fmaf(wk, bf_lo(n.x), a0.x);  a0.y = fmaf(wk, bf_hi(n.x), a0.y);
        a0.z = fmaf(wk, bf_lo(n.y), a0.z);  a0.w = fmaf(wk, bf_hi(n.y), a0.w);
        a1.x = fmaf(wk, bf_lo(n.z), a1.x);  a1.y = fmaf(wk, bf_hi(n.z), a1.y);
        a1.z = fmaf(wk, bf_lo(n.w), a1.z);  a1.w = fmaf(wk, bf_hi(n.w), a1.w);
    }

    float4* orow = (float4*)(out + (size_t)tok * C_DIM);
    __stcs(&orow[2*lane],     a0);
    __stcs(&orow[2*lane + 1], a1);
}

// ---------------------------------------------------------------------------
extern "C" void kernel_launch(void* const* d_in, const int* in_sizes, int n_in,
                              void* d_out, int out_size) {
    const float* x    = (const float*)d_in[0];
    const float* dist = (const float*)d_in[1];
    const int*   idx  = (const int*)  d_in[2];
    const float* rf   = (const float*)d_in[3];
    const float* w1   = (const float*)d_in[4];
    const float* w2   = (const float*)d_in[5];
    const float* bias = (const float*)d_in[6];
    float* out = (float*)d_out;

    prep_k<<<256 + (TOK_TOTAL * C_DIM / 4) / 256, 256>>>(dist, x);
    mbuild_k<<<128, 256>>>(w1, w2);
    rect1_k<<<TOK_TOTAL / 8, 256>>>(x, idx);
    gemm_k<<<TOK_TOTAL / 64, 256>>>(bias);
    k2_rect_add<<<TOK_TOTAL / 8, 256>>>(rf, idx, out);
}

// round 17
// speedup vs baseline: 1.4639x; 1.0465x over previous
#include <cuda_runtime.h>
#include <cuda_bf16.h>
#include <math.h>

// Problem constants: B=8, N=8192, C=256, K=8, nblocks=8, blk=32
#define TOK_TOTAL 65536          // B*N
#define N_TOK     8192
#define C_DIM     256
#define K_NB      8
#define EPS_W     0.05f
#define OME_W     0.95f

// Scratch (allocation-free rule: __device__ globals)
__device__ unsigned       g_s1h[(size_t)TOK_TOTAL * 128];   // 32 MB s1 bf16 hi (bf16x2)
__device__ unsigned       g_s1l[(size_t)TOK_TOTAL * 128];   // 32 MB s1 bf16 lo (bf16x2)
__device__ float          g_t [(size_t)TOK_TOTAL * C_DIM];  // 64 MB monarch out (f32)
__device__ __nv_bfloat16  g_th[(size_t)TOK_TOTAL * C_DIM];  // 32 MB bf16 shadow of t
__device__ __nv_bfloat16  g_xh[(size_t)TOK_TOTAL * C_DIM];  // 32 MB bf16 shadow of x
__device__ float          g_w [(size_t)TOK_TOTAL * K_NB];   // eps-scaled softmax weights
// Combined monarch matrix M (256x256) in mma B-fragment order, hi/lo
// interleaved per fragment pair: uint4 = {b0_hi, b1_hi, b0_lo, b1_lo}.
__device__ unsigned       g_MF[131072];                     // 512 KB

// bf16 -> f32 is exact: shift/mask into high mantissa bits (ALU pipe).
__device__ __forceinline__ float bf_lo(unsigned u) { return __uint_as_float(u << 16); }
__device__ __forceinline__ float bf_hi(unsigned u) { return __uint_as_float(u & 0xFFFF0000u); }

// pack two f32 into bf16x2 hi + exact-residual lo (elem0 -> low half; PTX cvt
// puts FIRST operand in the HIGH half, so pass (y, x)). Validated R14-R16.
__device__ __forceinline__ void split2(float2 v, unsigned& hi, unsigned& lo) {
    unsigned h, l;
    asm("cvt.rn.bf16x2.f32 %0, %1, %2;" : "=r"(h) : "f"(v.y), "f"(v.x));
    float rx = v.x - __uint_as_float(h << 16);          // exact residual
    float ry = v.y - __uint_as_float(h & 0xFFFF0000u);  // exact residual
    asm("cvt.rn.bf16x2.f32 %0, %1, %2;" : "=r"(l) : "f"(ry), "f"(rx));
    hi = h; lo = l;
}
__device__ __forceinline__ unsigned pack_bf(float lo_e, float hi_e) {
    unsigned r;
    asm("cvt.rn.bf16x2.f32 %0, %1, %2;" : "=r"(r) : "f"(hi_e), "f"(lo_e));
    return r;
}
__device__ __forceinline__ void mma_bf16(float* d, const unsigned* a,
                                         unsigned b0, unsigned b1) {
    asm volatile(
        "mma.sync.aligned.m16n8k16.row.col.f32.bf16.bf16.f32 "
        "{%0,%1,%2,%3}, {%4,%5,%6,%7}, {%8,%9}, {%0,%1,%2,%3};"
        : "+f"(d[0]), "+f"(d[1]), "+f"(d[2]), "+f"(d[3])
        : "r"(a[0]), "r"(a[1]), "r"(a[2]), "r"(a[3]), "r"(b0), "r"(b1));
}

// ---------------------------------------------------------------------------
// Kernel 0 (prep): blocks [0,256) compute eps*softmax(-distance);
// blocks [256, 256+16384) convert x (f32) -> g_xh (bf16).
// ---------------------------------------------------------------------------
__global__ void prep_k(const float* __restrict__ dist, const float* __restrict__ x) {
    if (blockIdx.x < 256) {
        int tok = blockIdx.x * blockDim.x + threadIdx.x;
        const float4* dp = (const float4*)(dist + (size_t)tok * K_NB);
        float4 a = dp[0], b4 = dp[1];
        float d[8] = {a.x, a.y, a.z, a.w, b4.x, b4.y, b4.z, b4.w};
        float e[8];
        float s = 0.f;
#pragma unroll
        for (int k = 0; k < 8; k++) { e[k] = __expf(-d[k]); s += e[k]; }
        float inv = EPS_W / s;
        float4* wp = (float4*)(g_w + (size_t)tok * K_NB);
        wp[0] = make_float4(e[0]*inv, e[1]*inv, e[2]*inv, e[3]*inv);
        wp[1] = make_float4(e[4]*inv, e[5]*inv, e[6]*inv, e[7]*inv);
    } else {
        size_t i = (size_t)(blockIdx.x - 256) * blockDim.x + threadIdx.x; // float4 id
        float4 f = __ldcs(&((const float4*)x)[i]);
        __nv_bfloat162 h0 = __float22bfloat162_rn(make_float2(f.x, f.y));
        __nv_bfloat162 h1 = __float22bfloat162_rn(make_float2(f.z, f.w));
        uint2 o;
        o.x = *reinterpret_cast<unsigned*>(&h0);
        o.y = *reinterpret_cast<unsigned*>(&h1);
        ((uint2*)g_xh)[i] = o;
    }
}

// ---------------------------------------------------------------------------
// Kernel 0b: build combined monarch matrix M (out 256 x in 256), split to
// bf16 hi/lo, stored in interleaved mma B-fragment order.
//   n = s*8+l (out), k = a*32+p (in):
//   M[n][k] = sum_{j=0..3} w2[l,s,4a+j] * w1[a, 8j+l, p]
// ---------------------------------------------------------------------------
__global__ void mbuild_k(const float* __restrict__ w1,
                         const float* __restrict__ w2) {
    const int u = blockIdx.x * blockDim.x + threadIdx.x;   // 0..32767
    const int b01  = u & 1;
    const int lane = (u >> 1) & 31;
    const int kc   = (u >> 6) & 15;
    const int ntg  = u >> 10;                 // 0..31
    const int n = ntg * 8 + (lane >> 2);
    const int k = kc * 16 + b01 * 8 + 2 * (lane & 3);

    const int l = n & 7, s = n >> 3;
    const int a = k >> 5, p = k & 31;
    const float* w2r = w2 + l * 1024 + s * 32 + 4 * a;
    const float* w1b = w1 + a * 1024 + l * 32 + p;   // + j*256 gives row 8j+l
    float m0 = 0.f, m1 = 0.f;
#pragma unroll
    for (int j = 0; j < 4; j++) {
        float c = w2r[j];
        m0 = fmaf(c, w1b[j * 256],     m0);
        m1 = fmaf(c, w1b[j * 256 + 1], m1);
    }
    unsigned hi, lo;
    split2(make_float2(m0, m1), hi, lo);
    g_MF[(u >> 1) * 4 + b01]     = hi;
    g_MF[(u >> 1) * 4 + 2 + b01] = lo;
}

// ---------------------------------------------------------------------------
// Kernel 1a: rectify1, warp-per-token, barrier-free, batched gathers.
// Output: s1 pre-split into bf16 hi/lo planes (exact residual).
// ---------------------------------------------------------------------------
__global__ void __launch_bounds__(256) rect1_k(
        const float* __restrict__ x,
        const int*   __restrict__ idx) {
    const int lane = threadIdx.x & 31;
    const int warp = threadIdx.x >> 5;
    const int tok  = blockIdx.x * 8 + warp;     // grid = TOK_TOTAL/8
    const int b    = tok >> 13;
    const __nv_bfloat16* xb = g_xh + ((size_t)b << 13) * C_DIM;

    float wv = 0.f; int iv = 0;
    if (lane < 8) {
        wv = g_w[(size_t)tok * 8 + lane];
        iv = idx[(size_t)tok * 8 + lane];
    }
    float wks[8]; const __nv_bfloat16* nps[8];
#pragma unroll
    for (int k = 0; k < 8; k++) {
        wks[k] = __shfl_sync(0xFFFFFFFFu, wv, k);
        nps[k] = xb + (size_t)__shfl_sync(0xFFFFFFFFu, iv, k) * C_DIM;
    }

    const float4* srow = (const float4*)(x + (size_t)tok * C_DIM);
    float4 s0 = __ldcs(&srow[2*lane]), s1 = __ldcs(&srow[2*lane + 1]);
    uint4 nv[8];
#pragma unroll
    for (int k = 0; k < 8; k++) nv[k] = ((const uint4*)nps[k])[lane];

    float4 a0 = make_float4(OME_W*s0.x, OME_W*s0.y, OME_W*s0.z, OME_W*s0.w);
    float4 a1 = make_float4(OME_W*s1.x, OME_W*s1.y, OME_W*s1.z, OME_W*s1.w);
#pragma unroll
    for (int k = 0; k < 8; k++) {
        float wk = wks[k]; uint4 n = nv[k];
        a0.x = fmaf(wk, bf_lo(n.x), a0.x);  a0.y = fmaf(wk, bf_hi(n.x), a0.y);
        a0.z = fmaf(wk, bf_lo(n.y), a0.z);  a0.w = fmaf(wk, bf_hi(n.y), a0.w);
        a1.x = fmaf(wk, bf_lo(n.z), a1.x);  a1.y = fmaf(wk, bf_hi(n.z), a1.y);
        a1.z = fmaf(wk, bf_lo(n.w), a1.z);  a1.w = fmaf(wk, bf_hi(n.w), a1.w);
    }

    unsigned h0,h1,h2,h3, l0,l1,l2,l3;
    split2(make_float2(a0.x, a0.y), h0, l0);
    split2(make_float2(a0.z, a0.w), h1, l1);
    split2(make_float2(a1.x, a1.y), h2, l2);
    split2(make_float2(a1.z, a1.w), h3, l3);
    __stcs(&((uint4*)g_s1h)[(size_t)tok * 32 + lane], make_uint4(h0,h1,h2,h3));
    __stcs(&((uint4*)g_s1l)[(size_t)tok * 32 + lane], make_uint4(l0,l1,l2,l3));
}

// ---------------------------------------------------------------------------
// Kernel 1b: monarch as ONE dense 256x256 GEMM on tensor cores.
// Y[tok][n] = sum_k s1[tok][k] * M[n][k] + bias[n]
// bf16 split-precision: D = Ah*Bh + Ah*Bl + Al*Bh (lo*lo dropped, ~2^-16).
// CTA = 64 tokens x 256 outs; warp w owns n-slice [w*32, w*32+32).
// k streamed in 32-wide chunks (8 barriers instead of 16); A staged in smem
// in FRAGMENT-CONTIGUOUS, XOR-swizzled order so each mma A-operand is one
// LDS.128, conflict-free. B: one LDG.128 per (nt,ks) per chunk, L2-resident.
// Fragment slot for (mg,ks,grp,tig): uint index
//   ((mg*2+ks)*8+grp)*16 + (tig^(grp&3))*4 + e,  e = a-register index 0..3.
// ---------------------------------------------------------------------------
__global__ void __launch_bounds__(256, 2) gemm_k(const float* __restrict__ bias) {
    __shared__ unsigned Ash[2][1024];   // 4 KB per buffer per plane
    __shared__ unsigned Asl[2][1024];

    const int tid  = threadIdx.x;
    const int lane = tid & 31;
    const int w    = tid >> 5;        // warp 0..7 -> n-slice
    const int grp  = lane >> 2;
    const int tig  = lane & 3;
    const int tok0 = blockIdx.x * 64;

    // bias per (nt, col-pair); D init (d0,d1 = row grp; d2,d3 = row grp+8)
    float D[4][4][4];
#pragma unroll
    for (int nt = 0; nt < 4; nt++) {
        const int c = w*32 + nt*8 + 2*tig;
        const float b0 = bias[c], b1 = bias[c + 1];
#pragma unroll
        for (int mg = 0; mg < 4; mg++) {
            D[mg][nt][0] = b0; D[mg][nt][1] = b1;
            D[mg][nt][2] = b0; D[mg][nt][3] = b1;
        }
    }

    // A staging role: thread (arow, aq) loads one uint4 (4 kpairs) per plane
    // per 32-k chunk and scatters it into fragment slots.
    const int arow = tid >> 2;        // 0..63
    const int aq   = tid & 3;         // 0..3 -> ks = aq>>1, half = aq&1
    const int mg_s  = arow >> 4;
    const int rr    = arow & 15;
    const int grp_s = rr & 7;
    const int eb    = rr >> 3;                    // row grp (+8) -> e parity
    const int ks_s  = aq >> 1;
    const int e_s   = (aq & 1) * 2 + eb;          // a-register index
    const int fb    = ((mg_s*2 + ks_s)*8 + grp_s) * 16;  // fragment base
    const int sw    = grp_s & 3;                  // XOR swizzle key
    const unsigned* hp = g_s1h + (size_t)(tok0 + arow) * 128;  // row base (uints)
    const unsigned* lp = g_s1l + (size_t)(tok0 + arow) * 128;

    uint4 pfh = __ldcs((const uint4*)hp + aq);
    uint4 pfl = __ldcs((const uint4*)lp + aq);
    {
        unsigned* dh = &Ash[0][fb + e_s];
        unsigned* dl = &Asl[0][fb + e_s];
        dh[(0^sw)*4] = pfh.x; dh[(1^sw)*4] = pfh.y; dh[(2^sw)*4] = pfh.z; dh[(3^sw)*4] = pfh.w;
        dl[(0^sw)*4] = pfl.x; dl[(1^sw)*4] = pfl.y; dl[(2^sw)*4] = pfl.z; dl[(3^sw)*4] = pfl.w;
    }

    const int lslot = (tig ^ (grp & 3)) * 4;      // this lane's fragment offset

#pragma unroll 1
    for (int c = 0; c < 8; c++) {
        if (c < 7) {
            pfh = __ldcs((const uint4*)hp + (c + 1) * 4 + aq);
            pfl = __ldcs((const uint4*)lp + (c + 1) * 4 + aq);
        }
        __syncthreads();   // buf c&1 staged; prior reads of it long done

        const unsigned* bufh = Ash[c & 1];
        const unsigned* bufl = Asl[c & 1];
#pragma unroll
        for (int ks = 0; ks < 2; ks++) {
            // B fragments for k-chunk kc = c*2+ks (hi/lo interleaved uint4)
            uint4 BF[4];
#pragma unroll
            for (int nt = 0; nt < 4; nt++)
                BF[nt] = ((const uint4*)g_MF)[(((w*4 + nt)*16 + c*2 + ks) << 5) + lane];
#pragma unroll
            for (int mg = 0; mg < 4; mg++) {
                const int fbase = ((mg*2 + ks)*8 + grp) * 16 + lslot;
                uint4 ah4 = *(const uint4*)&bufh[fbase];
                uint4 al4 = *(const uint4*)&bufl[fbase];
                const unsigned ah[4] = {ah4.x, ah4.y, ah4.z, ah4.w};
                const unsigned al[4] = {al4.x, al4.y, al4.z, al4.w};
#pragma unroll
                for (int nt = 0; nt < 4; nt++) {
                    mma_bf16(D[mg][nt], ah, BF[nt].x, BF[nt].y);
                    mma_bf16(D[mg][nt], ah, BF[nt].z, BF[nt].w);
                    mma_bf16(D[mg][nt], al, BF[nt].x, BF[nt].y);
                }
            }
        }
        if (c < 7) {
            unsigned* dh = &Ash[(c + 1) & 1][fb + e_s];
            unsigned* dl = &Asl[(c + 1) & 1][fb + e_s];
            dh[(0^sw)*4] = pfh.x; dh[(1^sw)*4] = pfh.y; dh[(2^sw)*4] = pfh.z; dh[(3^sw)*4] = pfh.w;
            dl[(0^sw)*4] = pfl.x; dl[(1^sw)*4] = pfl.y; dl[(2^sw)*4] = pfl.z; dl[(3^sw)*4] = pfl.w;
        }
    }

    // store: rows tok0+mg*16+grp (+8), cols w*32+nt*8+2tig (+1)
#pragma unroll
    for (int mg = 0; mg < 4; mg++) {
        const int row = tok0 + mg*16 + grp;
#pragma unroll
        for (int nt = 0; nt < 4; nt++) {
            const int cb = w*32 + nt*8 + 2*tig;
            const size_t o0 = (size_t)row * C_DIM + cb;
            const size_t o1 = (size_t)(row + 8) * C_DIM + cb;
            __stcs((float2*)&g_t[o0], make_float2(D[mg][nt][0], D[mg][nt][1]));
            __stcs((float2*)&g_t[o1], make_float2(D[mg][nt][2], D[mg][nt][3]));
            *(unsigned*)&g_th[o0] = pack_bf(D[mg][nt][0], D[mg][nt][1]);
            *(unsigned*)&g_th[o1] = pack_bf(D[mg][nt][2], D[mg][nt][3]);
        }
    }
}

// ---------------------------------------------------------------------------
// Kernel 2: rectify2 on t + rf. Warp-per-token, barrier-free, batched bf16
// gathers.
// ---------------------------------------------------------------------------
__global__ void __launch_bounds__(256) k2_rect_add(
        const float* __restrict__ rf,
        const int*   __restrict__ idx,
        float*       __restrict__ out) {
    const int lane = threadIdx.x & 31;
    const int warp = threadIdx.x >> 5;
    const int tok  = blockIdx.x * 8 + warp;     // grid = TOK_TOTAL/8
    const int b    = tok >> 13;
    const __nv_bfloat16* tb = g_th + ((size_t)b << 13) * C_DIM;

    float wv = 0.f; int iv = 0;
    if (lane < 8) {
        wv = g_w[(size_t)tok * 8 + lane];
        iv = idx[(size_t)tok * 8 + lane];
    }
    float wks[8]; const __nv_bfloat16* nps[8];
#pragma unroll
    for (int k = 0; k < 8; k++) {
        wks[k] = __shfl_sync(0xFFFFFFFFu, wv, k);
        nps[k] = tb + (size_t)__shfl_sync(0xFFFFFFFFu, iv, k) * C_DIM;
    }

    const float4* trow = (const float4*)(g_t + (size_t)tok * C_DIM);
    float4 s0 = __ldcs(&trow[2*lane]), s1 = __ldcs(&trow[2*lane + 1]);
    const float4* rrow = (const float4*)(rf + (size_t)tok * C_DIM);
    float4 r0 = __ldcs(&rrow[2*lane]), r1 = __ldcs(&rrow[2*lane + 1]);
    uint4 nv[8];
#pragma unroll
    for (int k = 0; k < 8; k++) nv[k] = ((const uint4*)nps[k])[lane];

    float4 a0 = make_float4(OME_W*s0.x + r0.x, OME_W*s0.y + r0.y,
                            OME_W*s0.z + r0.z, OME_W*s0.w + r0.w);
    float4 a1 = make_float4(OME_W*s1.x + r1.x, OME_W*s1.y + r1.y,
                            OME_W*s1.z + r1.z, OME_W*s1.w + r1.w);
#pragma unroll
    for (int k = 0; k < 8; k++) {
        float wk = wks[k]; uint4 n = nv[k];
        a0.x = fmaf(wk, bf_lo(n.x), a0.x);  a0.y = fmaf(wk, bf_hi(n.x), a0.y);
        a0.z = fmaf(wk, bf_lo(n.y), a0.z);  a0.w = fmaf(wk, bf_hi(n.y), a0.w);
        a1.x = fmaf(wk, bf_lo(n.z), a1.x);  a1.y = fmaf(wk, bf_hi(n.z), a1.y);
        a1.z = fmaf(wk, bf_lo(n.w), a1.z);  a1.w = fmaf(wk, bf_hi(n.w), a1.w);
    }

    float4* orow = (float4*)(out + (size_t)tok * C_DIM);
    __stcs(&orow[2*lane],     a0);
    __stcs(&orow[2*lane + 1], a1);
}

// ---------------------------------------------------------------------------
extern "C" void kernel_launch(void* const* d_in, const int* in_sizes, int n_in,
                              void* d_out, int out_size) {
    const float* x    = (const float*)d_in[0];
    const float* dist = (const float*)d_in[1];
    const int*   idx  = (const int*)  d_in[2];
    const float* rf   = (const float*)d_in[3];
    const float* w1   = (const float*)d_in[4];
    const float* w2   = (const float*)d_in[5];
    const float* bias = (const float*)d_in[6];
    float* out = (float*)d_out;

    prep_k<<<256 + (TOK_TOTAL * C_DIM / 4) / 256, 256>>>(dist, x);
    mbuild_k<<<128, 256>>>(w1, w2);
    rect1_k<<<TOK_TOTAL / 8, 256>>>(x, idx);
    gemm_k<<<TOK_TOTAL / 64, 256>>>(bias);
    k2_rect_add<<<TOK_TOTAL / 8, 256>>>(rf, idx, out);
}